// round 7
// baseline (speedup 1.0000x reference)
#include <cuda_runtime.h>
#include <math.h>

#define B_ 16
#define C_ 128
#define T_ 25
#define J_ 25
#define N_ 25
#define F_ 256
#define NB_S (B_*T_)   // 400 spatial tiles
#define XS_STRIDE 132  // floats per smem row (128 + 4 pad, float4 compatible)
#define GRID_ (16 + 1 + NB_S)   // 417 blocks: 16 w, 1 posd, 400 spatial+temporal

// Precomputed device-global scratch (static __device__ arrays: allowed)
__device__ float g_w1s[C_], g_w2s[C_], g_w1t[C_], g_w2t[C_];
__device__ float g_posd1[T_], g_posd2[T_];
__device__ float4 g_srcT4[B_ * J_ * T_ * (C_ / 4)];   // srcT[b][j][t][c], 5.12 MB

// Cross-block sync state (zero at load; last exiting block resets -> every
// graph replay starts from zero).
__device__ int g_cnt_ws = 0;          // -> 8 when spatial w vectors ready
__device__ int g_cnt_wt = 0;          // -> 8 when temporal w vectors ready
__device__ int g_cnt_stage_b[B_];     // per-b staging counters, each -> 25
__device__ int g_flag_posd = 0;       // -> 1 when posd constants written
__device__ int g_cnt_done = 0;        // completion counter for reset

// Poll with plain strong loads (no RMW -> no LTS atomic serialization).
__device__ __forceinline__ void wait_ge(const int* p, int target) {
    const volatile int* vp = (const volatile int*)p;
    while (*vp < target) __nanosleep(64);
}

// ---------------------------------------------------------------------------
// ONE fused kernel. Roles by blockIdx.x:
//   0..7    : spatial w = Ws@as halves
//   8..15   : temporal w = Wt@at halves
//   16      : posd constants (fp64 sinusoid table FIRST, then wait for wt)
//   17..416 : spatial tile (b,t)  ->  then temporal tile (b, j=t)
// All 417 blocks co-resident (smem ~17.4KB -> 13/SM possible, need 3), so
// spin-waits cannot deadlock.
// ---------------------------------------------------------------------------
__global__ void __launch_bounds__(128) fused_kernel(const float* __restrict__ src,
                                                    const float* __restrict__ Ws,
                                                    const float* __restrict__ as_,
                                                    const float* __restrict__ Wt,
                                                    const float* __restrict__ at_,
                                                    float* __restrict__ out) {
    __shared__ float4 xs4[N_ * (XS_STRIDE / 4)];   // 13200 B (aliased by posd)
    __shared__ float s1[N_], s2[N_];
    __shared__ float ee[N_ * N_];
    __shared__ float w1[C_], w2[C_];
    __shared__ float pd1[T_], pd2[T_];
    __shared__ float sumw1, sumw2;

    int bid = blockIdx.x;
    int tid = threadIdx.x;
    int wid = tid >> 5;
    int lane = tid & 31;

    if (bid < 16) {
        // ------------------- W-dot blocks -------------------
        bool is_s = bid < 8;
        const float* W = is_s ? Ws : Wt;
        const float* a = is_s ? as_ : at_;
        float* o1 = is_s ? g_w1s : g_w1t;
        float* o2 = is_s ? g_w2s : g_w2t;
        int* ctr = is_s ? &g_cnt_ws : &g_cnt_wt;
        int row0 = (bid & 7) * 16;

        float a1v[8], a2v[8];
        #pragma unroll
        for (int u = 0; u < 8; ++u) {
            a1v[u] = __ldg(a + lane + 32 * u);
            a2v[u] = __ldg(a + F_ + lane + 32 * u);
        }
        #pragma unroll
        for (int k = 0; k < 4; ++k) {
            int row = row0 + wid * 4 + k;
            const float* Wrow = W + (size_t)row * F_;
            float acc1 = 0.f, acc2 = 0.f;
            #pragma unroll
            for (int u = 0; u < 8; ++u) {
                float wv = __ldg(Wrow + lane + 32 * u);
                acc1 = fmaf(wv, a1v[u], acc1);
                acc2 = fmaf(wv, a2v[u], acc2);
            }
            #pragma unroll
            for (int off = 16; off > 0; off >>= 1) {
                acc1 += __shfl_xor_sync(0xffffffffu, acc1, off);
                acc2 += __shfl_xor_sync(0xffffffffu, acc2, off);
            }
            if (lane == 0) { o1[row] = acc1; o2[row] = acc2; }
        }
        __syncthreads();
        if (tid == 0) { __threadfence(); atomicAdd(ctr, 1); }
    } else if (bid == 16) {
        // ------------------- posd block -------------------
        // Phase A (independent of w): fp64 sinusoid table into smem.
        //   scf[t*128 + 2h2]   = f32(sin(t/denom)) * 1000f
        //   scf[t*128 + 2h2+1] = f32(cos(t/denom)) * 1000f
        float* scf = (float*)xs4;      // [25][128] floats = 12800 B
        if (tid < C_ / 2) {
            int h2 = tid;
            // denom = 10000^(h2/64) = 10^(h2/16), square-and-multiply.
            double denom = 1.0;
            if (h2 & 1)  denom *= 1.1547819846894583;   // 10^(1/16)
            if (h2 & 2)  denom *= 1.3335214321633240;   // 10^(1/8)
            if (h2 & 4)  denom *= 1.7782794100389228;   // 10^(1/4)
            if (h2 & 8)  denom *= 3.1622776601683795;   // 10^(1/2)
            if (h2 & 16) denom *= 10.0;
            if (h2 & 32) denom *= 100.0;
            double S, Cc;
            sincos(1.0 / denom, &S, &Cc);
            double s = 0.0, c = 1.0;                    // t=0: sin=0, cos=1
            for (int t = 0; t < T_; ++t) {
                scf[t * C_ + 2 * h2]     = (float)s * 1000.0f;
                scf[t * C_ + 2 * h2 + 1] = (float)c * 1000.0f;
                double ns = s * Cc + c * S;             // angle-addition step
                double nc = c * Cc - s * S;
                s = ns; c = nc;
            }
        }
        // Phase B: wait for temporal w, then fp64 dot per (t, which).
        if (tid == 0) wait_ge(&g_cnt_wt, 8);
        __syncthreads();
        __threadfence();
        if (tid < 2 * T_) {
            int t = tid >> 1;
            const float* wv = (tid & 1) ? g_w2t : g_w1t;
            const float* row = scf + t * C_;
            double a0 = 0.0, a1 = 0.0, a2 = 0.0, a3 = 0.0;
            #pragma unroll
            for (int h = 0; h < C_; h += 4) {
                a0 += (double)row[h]     * (double)wv[h];
                a1 += (double)row[h + 1] * (double)wv[h + 1];
                a2 += (double)row[h + 2] * (double)wv[h + 2];
                a3 += (double)row[h + 3] * (double)wv[h + 3];
            }
            float r = (float)((a0 + a1) + (a2 + a3));
            if (tid & 1) g_posd2[t] = r; else g_posd1[t] = r;
        }
        __syncthreads();
        if (tid == 0) { __threadfence(); atomicAdd(&g_flag_posd, 1); }
    } else {
        // ------------- merged spatial (b,t) + temporal (b,j=t) -------------
        int sb = bid - 17;
        int b = sb / T_, t = sb % T_;
        const float* base = src + (size_t)b * (C_ * T_ * J_) + t * J_;  // +c*625+j
        float* xs = (float*)xs4;

        // 1) independent work: gather x[j][c] (25-float runs along j)
        for (int i = tid; i < N_ * C_; i += 128) {
            int c = i / N_, n = i % N_;
            xs[n * XS_STRIDE + c] = __ldg(base + c * (T_ * J_) + n);
        }
        __syncthreads();

        // 2) transposed staging write: srcT[b][j][t][c], coalesced 512B rows
        {
            float4* dst = g_srcT4 + ((size_t)b * J_) * (T_ * 32) + t * 32;
            for (int i = tid; i < N_ * 32; i += 128) {
                int j = i >> 5, c4 = i & 31;
                dst[(size_t)j * (T_ * 32) + c4] = xs4[j * (XS_STRIDE / 4) + c4];
            }
        }
        if (tid == 0) {
            __threadfence();
            atomicAdd(&g_cnt_stage_b[b], 1);
            wait_ge(&g_cnt_ws, 8);       // 3) wait for spatial w vectors
        }
        __syncthreads();
        __threadfence();

        w1[tid] = g_w1s[tid];
        w2[tid] = g_w2s[tid];
        __syncthreads();
        if (wid == 0) {   // sum of w vectors (for the spatial-PE scalar term)
            float v1 = w1[lane] + w1[lane+32] + w1[lane+64] + w1[lane+96];
            float v2 = w2[lane] + w2[lane+32] + w2[lane+64] + w2[lane+96];
            #pragma unroll
            for (int off = 16; off > 0; off >>= 1) {
                v1 += __shfl_xor_sync(0xffffffffu, v1, off);
                v2 += __shfl_xor_sync(0xffffffffu, v2, off);
            }
            if (lane == 0) { sumw1 = v1; sumw2 = v2; }
        }
        __syncthreads();

        // warp-parallel per-node dots (+ PE distance to node 8)
        for (int n = wid; n < N_; n += 4) {
            float acc1 = 0.f, acc2 = 0.f, ss = 0.f;
            float4 xv4 = xs4[n * (XS_STRIDE / 4) + lane];
            float4 x84 = xs4[8 * (XS_STRIDE / 4) + lane];
            const float* xv = (const float*)&xv4;
            const float* x8 = (const float*)&x84;
            #pragma unroll
            for (int k = 0; k < 4; ++k) {
                int c = 4 * lane + k;
                acc1 = fmaf(xv[k], w1[c], acc1);
                acc2 = fmaf(xv[k], w2[c], acc2);
                float d = xv[k] - x8[k];
                ss = fmaf(d, d, ss);
            }
            #pragma unroll
            for (int off = 16; off > 0; off >>= 1) {
                acc1 += __shfl_xor_sync(0xffffffffu, acc1, off);
                acc2 += __shfl_xor_sync(0xffffffffu, acc2, off);
                ss   += __shfl_xor_sync(0xffffffffu, ss,   off);
            }
            if (lane == 0) {
                float delta = expf(-sqrtf(ss) * 0.001f);
                s1[n] = fmaf(delta, sumw1, acc1);
                s2[n] = fmaf(delta, sumw2, acc2);
            }
        }
        __syncthreads();

        for (int i = tid; i < N_ * N_; i += 128) {
            int p = i / N_, q = i % N_;
            int k1 = 2 * p * N_ + 2 * q;
            int k2 = k1 + 1;
            int n1 = (k1 < N_*N_) ? (k1 / N_) : ((k1 - N_*N_) % N_);
            int n2 = (k2 < N_*N_) ? (k2 / N_) : ((k2 - N_*N_) % N_);
            float v = s1[n1] + s2[n2];
            ee[i] = (v >= 0.f) ? v : 0.2f * v;
        }
        __syncthreads();

        if (tid < N_) {
            int q = tid;
            float v[N_];
            float m = -3.402823466e38f;
            #pragma unroll
            for (int p = 0; p < N_; ++p) { v[p] = ee[p*N_+q]; m = fmaxf(m, v[p]); }
            float s = 0.f;
            #pragma unroll
            for (int p = 0; p < N_; ++p) { v[p] = expf(v[p] - m); s += v[p]; }
            float inv = 1.f / s;
            float m2 = -3.402823466e38f;
            #pragma unroll
            for (int p = 0; p < N_; ++p) { v[p] *= inv; m2 = fmaxf(m2, v[p]); }
            float s2v = 0.f;
            #pragma unroll
            for (int p = 0; p < N_; ++p) { v[p] = expf(v[p] - m2); s2v += v[p]; }
            float inv2 = 1.f / s2v;
            float* o = out + (size_t)sb * (N_ * N_);
            #pragma unroll
            for (int p = 0; p < N_; ++p) o[p * N_ + q] = v[p] * inv2;
        }

        // ---------------- temporal phase: tile (b, j=t) ----------------
        int j = t;
        if (tid == 0) {
            wait_ge(&g_cnt_stage_b[b], T_);   // only THIS b's 25 producers
            wait_ge(&g_flag_posd, 1);
        }
        __syncthreads();
        __threadfence();

        w1[tid] = g_w1t[tid];
        w2[tid] = g_w2t[tid];
        if (tid < T_) { pd1[tid] = g_posd1[tid]; pd2[tid] = g_posd2[tid]; }

        const float4* basev = g_srcT4 + ((size_t)b * J_ + j) * (T_ * 32);
        for (int i = tid; i < T_ * 32; i += 128) {
            xs4[(i >> 5) * (XS_STRIDE / 4) + (i & 31)] = basev[i];
        }
        __syncthreads();

        for (int n = wid; n < T_; n += 4) {
            float acc1 = 0.f, acc2 = 0.f;
            float4 xv4 = xs4[n * (XS_STRIDE / 4) + lane];
            const float* xv = (const float*)&xv4;
            #pragma unroll
            for (int k = 0; k < 4; ++k) {
                int c = 4 * lane + k;
                acc1 = fmaf(xv[k], w1[c], acc1);
                acc2 = fmaf(xv[k], w2[c], acc2);
            }
            #pragma unroll
            for (int off = 16; off > 0; off >>= 1) {
                acc1 += __shfl_xor_sync(0xffffffffu, acc1, off);
                acc2 += __shfl_xor_sync(0xffffffffu, acc2, off);
            }
            if (lane == 0) {
                s1[n] = acc1 + pd1[n];
                s2[n] = acc2 + pd2[n];
            }
        }
        __syncthreads();

        for (int i = tid; i < N_ * N_; i += 128) {
            int p = i / N_, q = i % N_;
            int k1 = 2 * p * N_ + 2 * q;
            int k2 = k1 + 1;
            int n1 = (k1 < N_*N_) ? (k1 / N_) : ((k1 - N_*N_) % N_);
            int n2 = (k2 < N_*N_) ? (k2 / N_) : ((k2 - N_*N_) % N_);
            float v = s1[n1] + s2[n2];
            ee[i] = (v >= 0.f) ? v : 0.2f * v;
        }
        __syncthreads();

        if (tid < N_) {
            int q = tid;
            float v[N_];
            float m = -3.402823466e38f;
            #pragma unroll
            for (int p = 0; p < N_; ++p) { v[p] = ee[p*N_+q]; m = fmaxf(m, v[p]); }
            float s = 0.f;
            #pragma unroll
            for (int p = 0; p < N_; ++p) { v[p] = expf(v[p] - m); s += v[p]; }
            float inv = 1.f / s;
            float m2 = -3.402823466e38f;
            #pragma unroll
            for (int p = 0; p < N_; ++p) { v[p] *= inv; m2 = fmaxf(m2, v[p]); }
            float s2v = 0.f;
            #pragma unroll
            for (int p = 0; p < N_; ++p) { v[p] = expf(v[p] - m2); s2v += v[p]; }
            float inv2 = 1.f / s2v;
            float* o = out + (size_t)(NB_S + sb) * (N_ * N_);
            #pragma unroll
            for (int p = 0; p < N_; ++p) o[p * N_ + q] = v[p] * inv2;
        }
    }

    // -------- reset sync state for the next (graph-replayed) launch --------
    __syncthreads();
    if (tid == 0) {
        __threadfence();
        int d = atomicAdd(&g_cnt_done, 1);
        if (d == GRID_ - 1) {
            g_cnt_ws = 0;
            g_cnt_wt = 0;
            g_flag_posd = 0;
            #pragma unroll
            for (int i = 0; i < B_; ++i) g_cnt_stage_b[i] = 0;
            __threadfence();
            g_cnt_done = 0;
        }
    }
}

extern "C" void kernel_launch(void* const* d_in, const int* in_sizes, int n_in,
                              void* d_out, int out_size) {
    const float* src = (const float*)d_in[0];
    const float* Ws  = (const float*)d_in[1];
    const float* as_ = (const float*)d_in[2];
    const float* Wt  = (const float*)d_in[3];
    const float* at_ = (const float*)d_in[4];
    float* out = (float*)d_out;

    fused_kernel<<<GRID_, 128>>>(src, Ws, as_, Wt, at_, out);
}